// round 11
// baseline (speedup 1.0000x reference)
#include <cuda_runtime.h>
#include <cuda_bf16.h>
#include <math.h>
#include <stdint.h>

// Problem constants
#define NROWS 32768      // rows in x (and in x_pair)
#define DDIM  256        // feature dim
#define NB    128        // 2B batches
#define MSZ   512        // mask size
#define EPSN  1e-8f

// Scratch
__device__ __align__(16) __nv_bfloat16 g_z[(size_t)NB * MSZ * DDIM];
__device__ float g_pos_partials[4096];
__device__ float g_rowsum[NB * MSZ];       // per-(b,row) sum of exp (2 contributions)
__device__ float g_lse_partials[256];

__device__ __forceinline__ uint32_t smem_u32(const void* p) {
    uint32_t a;
    asm("{ .reg .u64 t; cvta.to.shared.u64 t, %1; cvt.u32.u64 %0, t; }" : "=r"(a) : "l"(p));
    return a;
}

// ---------------------------------------------------------------------------
// Kernel 1: per-row L2 normalize -> bf16 per-batch layout + pos partials
//           + zero g_rowsum
// ---------------------------------------------------------------------------
__device__ __forceinline__ void store_bf16x4(__nv_bfloat16* dst, int idx4,
                                             float4 v, float scale) {
    __nv_bfloat162 lo = __floats2bfloat162_rn(v.x * scale, v.y * scale);
    __nv_bfloat162 hi = __floats2bfloat162_rn(v.z * scale, v.w * scale);
    uint2 packed;
    packed.x = *reinterpret_cast<uint32_t*>(&lo);
    packed.y = *reinterpret_cast<uint32_t*>(&hi);
    reinterpret_cast<uint2*>(dst)[idx4] = packed;
}

__global__ __launch_bounds__(256) void k_prep(const float* __restrict__ x,
                                              const float* __restrict__ xp) {
    int wid  = threadIdx.x >> 5;
    int lane = threadIdx.x & 31;
    int row  = blockIdx.x * 8 + wid;

    // zero the rowsum accumulator (65536 floats / 4096 blocks = 16 per block)
    if (threadIdx.x < 16) g_rowsum[blockIdx.x * 16 + threadIdx.x] = 0.f;

    const float4* xr = reinterpret_cast<const float4*>(x)  + (size_t)row * (DDIM / 4);
    const float4* pr = reinterpret_cast<const float4*>(xp) + (size_t)row * (DDIM / 4);

    float4 a0 = xr[lane];
    float4 a1 = xr[lane + 32];
    float4 b0 = pr[lane];
    float4 b1 = pr[lane + 32];

    float sx = a0.x*a0.x + a0.y*a0.y + a0.z*a0.z + a0.w*a0.w
             + a1.x*a1.x + a1.y*a1.y + a1.z*a1.z + a1.w*a1.w;
    float sp = b0.x*b0.x + b0.y*b0.y + b0.z*b0.z + b0.w*b0.w
             + b1.x*b1.x + b1.y*b1.y + b1.z*b1.z + b1.w*b1.w;
    float dp = a0.x*b0.x + a0.y*b0.y + a0.z*b0.z + a0.w*b0.w
             + a1.x*b1.x + a1.y*b1.y + a1.z*b1.z + a1.w*b1.w;

    #pragma unroll
    for (int o = 16; o > 0; o >>= 1) {
        sx += __shfl_xor_sync(0xFFFFFFFFu, sx, o);
        sp += __shfl_xor_sync(0xFFFFFFFFu, sp, o);
        dp += __shfl_xor_sync(0xFFFFFFFFu, dp, o);
    }

    float ix = 1.0f / fmaxf(sqrtf(sx), EPSN);
    float ip = 1.0f / fmaxf(sqrtf(sp), EPSN);

    // z[b, gi] = x[gi*128 + b]; z[b, 256+gi] = x_pair[gi*128 + b]
    int b  = row & 127;
    int gi = row >> 7;
    __nv_bfloat16* on = g_z + ((size_t)b * MSZ + gi) * DDIM;
    __nv_bfloat16* op = g_z + ((size_t)b * MSZ + 256 + gi) * DDIM;
    store_bf16x4(on, lane,      a0, ix);
    store_bf16x4(on, lane + 32, a1, ix);
    store_bf16x4(op, lane,      b0, ip);
    store_bf16x4(op, lane + 32, b1, ip);

    __shared__ float sm[8];
    if (lane == 0) sm[wid] = dp * ix * ip;
    __syncthreads();
    if (threadIdx.x == 0) {
        float t = 0.f;
        #pragma unroll
        for (int i = 0; i < 8; ++i) t += sm[i];
        g_pos_partials[blockIdx.x] = t;
    }
}

// ---------------------------------------------------------------------------
// Kernel 2: gram tiles via mma.sync bf16
// item = (batch, 64-row i-tile, 256-col j-half): 128*8*2 = 2048 CTAs
// 256 threads (8 warps: 2 M-slices x 4 N-slices of a 64x64 chunk)
// SMEM: A tile 64x256 bf16 + B double buffer (2 x 64-row chunks) = 101,376 B
// -> 2 CTAs/SM
// ---------------------------------------------------------------------------
#define AB_STRIDE 528                 // 512B row + 16B pad (conflict-free ldmatrix)
#define CH_B      (64 * AB_STRIDE)    // 33,792 B per 64-row tile
#define SMEM_DYN  (3 * CH_B)          // 101,376 B

__device__ __forceinline__ void cp_tile64(char* dst, const char* src, int tid) {
    uint32_t d = smem_u32(dst);
    #pragma unroll
    for (int i = 0; i < 8; ++i) {
        int idx = tid + i * 256;       // 0..2047: 64 rows x 32 segs of 16B
        int row = idx >> 5;
        int seg = idx & 31;
        asm volatile("cp.async.cg.shared.global [%0], [%1], 16;"
                     :: "r"(d + row * AB_STRIDE + seg * 16),
                        "l"(src + (size_t)row * 512 + seg * 16) : "memory");
    }
}
#define CP_COMMIT() asm volatile("cp.async.commit_group;" ::: "memory")

__device__ __forceinline__ void ldsm_x4(uint32_t* r, uint32_t addr) {
    asm volatile("ldmatrix.sync.aligned.m8n8.x4.shared.b16 {%0,%1,%2,%3}, [%4];"
                 : "=r"(r[0]), "=r"(r[1]), "=r"(r[2]), "=r"(r[3]) : "r"(addr));
}
__device__ __forceinline__ void mma16816(float* c, const uint32_t* a,
                                         uint32_t b0, uint32_t b1) {
    asm volatile("mma.sync.aligned.m16n8k16.row.col.f32.bf16.bf16.f32 "
                 "{%0,%1,%2,%3}, {%4,%5,%6,%7}, {%8,%9}, {%0,%1,%2,%3};"
                 : "+f"(c[0]), "+f"(c[1]), "+f"(c[2]), "+f"(c[3])
                 : "r"(a[0]), "r"(a[1]), "r"(a[2]), "r"(a[3]), "r"(b0), "r"(b1));
}

__global__ __launch_bounds__(256) void k_neg() {
    extern __shared__ char smraw[];
    char* sA = smraw;
    char* sBb[2] = { smraw + CH_B, smraw + 2 * CH_B };
    __shared__ float s_part[4][64];    // [warp_n][row] partial rowsums

    const int tid    = threadIdx.x;
    const int w      = tid >> 5;
    const int lane   = tid & 31;
    const int b      = blockIdx.x >> 4;
    const int it     = (blockIdx.x >> 1) & 7;   // 64-row i-tile
    const int jh     = blockIdx.x & 1;          // 256-col j-half
    const int warp_m = w & 1;                   // 2 M-slices of 32 rows
    const int warp_n = w >> 1;                  // 4 N-slices of 16 cols

    const char* zb = reinterpret_cast<const char*>(g_z) + (size_t)b * MSZ * DDIM * 2;

    // prefetch A(i-tile) and B chunk 0 as group 0
    cp_tile64(sA, zb + (size_t)it * 64 * 512, tid);
    cp_tile64(sBb[0], zb + (size_t)jh * 256 * 512, tid);
    CP_COMMIT();

    const uint32_t aBase = smem_u32(sA)
        + (uint32_t)(warp_m * 32 + (lane & 15)) * AB_STRIDE + (uint32_t)(lane >> 4) * 16;
    const uint32_t bOff  =
          (uint32_t)(warp_n * 16 + (lane >> 4) * 8 + (lane & 7)) * AB_STRIDE
        + (uint32_t)((lane >> 3) & 1) * 16;

    float racc[4] = {0.f, 0.f, 0.f, 0.f};   // [mi][rowhalf] row partials

    #pragma unroll
    for (int c = 0; c < 4; ++c) {
        if (c < 3) {
            cp_tile64(sBb[(c + 1) & 1], zb + (size_t)(jh * 256 + (c + 1) * 64) * 512, tid);
            CP_COMMIT();
            asm volatile("cp.async.wait_group 1;" ::: "memory");
        } else {
            asm volatile("cp.async.wait_group 0;" ::: "memory");
        }
        __syncthreads();                       // B chunk c visible

        const uint32_t bBase = smem_u32(sBb[c & 1]) + bOff;

        float acc[2][2][4];
        #pragma unroll
        for (int mi = 0; mi < 2; ++mi)
            #pragma unroll
            for (int ni = 0; ni < 2; ++ni)
                #pragma unroll
                for (int q = 0; q < 4; ++q) acc[mi][ni][q] = 0.f;

        #pragma unroll 8
        for (int ks = 0; ks < 16; ++ks) {
            uint32_t af[2][4], bf[4];
            ldsm_x4(af[0], aBase + ks * 32);
            ldsm_x4(af[1], aBase + 16 * AB_STRIDE + ks * 32);
            ldsm_x4(bf, bBase + ks * 32);
            #pragma unroll
            for (int mi = 0; mi < 2; ++mi) {
                mma16816(acc[mi][0], af[mi], bf[0], bf[1]);
                mma16816(acc[mi][1], af[mi], bf[2], bf[3]);
            }
        }

        // epilogue: exp(2*dot), mask diagonal, accumulate row partials
        const int gj0 = jh * 256 + c * 64 + warp_n * 16 + (lane & 3) * 2;
        #pragma unroll
        for (int mi = 0; mi < 2; ++mi) {
            const int gi0 = it * 64 + warp_m * 32 + mi * 16 + (lane >> 2);
            #pragma unroll
            for (int ni = 0; ni < 2; ++ni) {
                const int gj = gj0 + ni * 8;
                float e00 = __expf(acc[mi][ni][0] * 2.f);
                float e01 = __expf(acc[mi][ni][1] * 2.f);
                float e10 = __expf(acc[mi][ni][2] * 2.f);
                float e11 = __expf(acc[mi][ni][3] * 2.f);
                if (gi0 == gj)         e00 = 0.f;
                if (gi0 == gj + 1)     e01 = 0.f;
                if (gi0 + 8 == gj)     e10 = 0.f;
                if (gi0 + 8 == gj + 1) e11 = 0.f;
                racc[mi * 2 + 0] += e00 + e01;
                racc[mi * 2 + 1] += e10 + e11;
            }
        }
        __syncthreads();                       // done reading sBb[c&1]
    }

    // quad reduce (cols within the warp), then deterministic fixed-order combine
    #pragma unroll
    for (int s = 0; s < 4; ++s) {
        racc[s] += __shfl_xor_sync(0xFFFFFFFFu, racc[s], 1);
        racc[s] += __shfl_xor_sync(0xFFFFFFFFu, racc[s], 2);
    }
    if ((lane & 3) == 0) {
        #pragma unroll
        for (int s = 0; s < 4; ++s) {
            int row = warp_m * 32 + (s >> 1) * 16 + (s & 1) * 8 + (lane >> 2);
            s_part[warp_n][row] = racc[s];     // unique (warp_n,row) slot
        }
    }
    __syncthreads();
    if (tid < 64) {
        float v = ((s_part[0][tid] + s_part[1][tid])
                 + (s_part[2][tid] + s_part[3][tid]));
        // 2 commutative adds per row across jh=0/1 -> deterministic
        atomicAdd(&g_rowsum[b * MSZ + it * 64 + tid], v);
    }
}

// ---------------------------------------------------------------------------
// Kernel 3: log of rowsums + block reduce
// ---------------------------------------------------------------------------
__global__ __launch_bounds__(256) void k_lse() {
    __shared__ float red[8];
    int tid = threadIdx.x;
    float v = logf(g_rowsum[blockIdx.x * 256 + tid]);
    #pragma unroll
    for (int o = 16; o > 0; o >>= 1) v += __shfl_xor_sync(0xFFFFFFFFu, v, o);
    if ((tid & 31) == 0) red[tid >> 5] = v;
    __syncthreads();
    if (tid == 0) {
        float t = 0.f;
        #pragma unroll
        for (int i = 0; i < 8; ++i) t += red[i];
        g_lse_partials[blockIdx.x] = t;
    }
}

// ---------------------------------------------------------------------------
// Kernel 4: final deterministic reduction -> scalar loss
// ---------------------------------------------------------------------------
__global__ __launch_bounds__(256) void k_final(float* __restrict__ out) {
    __shared__ float rp[256], rn[256];
    int tid = threadIdx.x;
    float sp = 0.f;
    for (int i = tid; i < 4096; i += 256) sp += g_pos_partials[i];
    rp[tid] = sp;
    rn[tid] = g_lse_partials[tid];
    __syncthreads();
    for (int o = 128; o > 0; o >>= 1) {
        if (tid < o) { rp[tid] += rp[tid + o]; rn[tid] += rn[tid + o]; }
        __syncthreads();
    }
    if (tid == 0) {
        float loss_neg = rn[0] / (float)(NB * MSZ);
        float loss_pos = rp[0] * 2.0f / (float)NROWS;
        out[0] = loss_neg - loss_pos;
    }
}

// ---------------------------------------------------------------------------
extern "C" void kernel_launch(void* const* d_in, const int* in_sizes, int n_in,
                              void* d_out, int out_size) {
    const float* x  = (const float*)d_in[0];
    const float* xp = (const float*)d_in[1];
    float* out = (float*)d_out;

    cudaFuncSetAttribute(k_neg, cudaFuncAttributeMaxDynamicSharedMemorySize, SMEM_DYN);

    k_prep<<<NROWS / 8, 256>>>(x, xp);
    k_neg<<<NB * 16, 256, SMEM_DYN>>>();
    k_lse<<<NB * MSZ / 256, 256>>>();
    k_final<<<1, 256>>>(out);
}

// round 13
// speedup vs baseline: 1.0962x; 1.0962x over previous
#include <cuda_runtime.h>
#include <cuda_bf16.h>
#include <math.h>
#include <stdint.h>

// Problem constants
#define NROWS 32768      // rows in x (and in x_pair)
#define DDIM  256        // feature dim
#define NB    128        // 2B batches
#define MSZ   512        // mask size
#define EPSN  1e-8f

// Scratch
__device__ __align__(16) __nv_bfloat16 g_z[(size_t)NB * MSZ * DDIM];
__device__ float g_pos_partials[4096];
__device__ float g_neg_partials[512];

__device__ __forceinline__ uint32_t smem_u32(const void* p) {
    uint32_t a;
    asm("{ .reg .u64 t; cvta.to.shared.u64 t, %1; cvt.u32.u64 %0, t; }" : "=r"(a) : "l"(p));
    return a;
}

// ---------------------------------------------------------------------------
// Kernel 1: per-row L2 normalize -> bf16 per-batch layout + pos partials
// ---------------------------------------------------------------------------
__device__ __forceinline__ void store_bf16x4(__nv_bfloat16* dst, int idx4,
                                             float4 v, float scale) {
    __nv_bfloat162 lo = __floats2bfloat162_rn(v.x * scale, v.y * scale);
    __nv_bfloat162 hi = __floats2bfloat162_rn(v.z * scale, v.w * scale);
    uint2 packed;
    packed.x = *reinterpret_cast<uint32_t*>(&lo);
    packed.y = *reinterpret_cast<uint32_t*>(&hi);
    reinterpret_cast<uint2*>(dst)[idx4] = packed;
}

__global__ __launch_bounds__(256) void k_prep(const float* __restrict__ x,
                                              const float* __restrict__ xp) {
    int wid  = threadIdx.x >> 5;
    int lane = threadIdx.x & 31;
    int row  = blockIdx.x * 8 + wid;

    const float4* xr = reinterpret_cast<const float4*>(x)  + (size_t)row * (DDIM / 4);
    const float4* pr = reinterpret_cast<const float4*>(xp) + (size_t)row * (DDIM / 4);

    float4 a0 = xr[lane];
    float4 a1 = xr[lane + 32];
    float4 b0 = pr[lane];
    float4 b1 = pr[lane + 32];

    float sx = a0.x*a0.x + a0.y*a0.y + a0.z*a0.z + a0.w*a0.w
             + a1.x*a1.x + a1.y*a1.y + a1.z*a1.z + a1.w*a1.w;
    float sp = b0.x*b0.x + b0.y*b0.y + b0.z*b0.z + b0.w*b0.w
             + b1.x*b1.x + b1.y*b1.y + b1.z*b1.z + b1.w*b1.w;
    float dp = a0.x*b0.x + a0.y*b0.y + a0.z*b0.z + a0.w*b0.w
             + a1.x*b1.x + a1.y*b1.y + a1.z*b1.z + a1.w*b1.w;

    #pragma unroll
    for (int o = 16; o > 0; o >>= 1) {
        sx += __shfl_xor_sync(0xFFFFFFFFu, sx, o);
        sp += __shfl_xor_sync(0xFFFFFFFFu, sp, o);
        dp += __shfl_xor_sync(0xFFFFFFFFu, dp, o);
    }

    float ix = 1.0f / fmaxf(sqrtf(sx), EPSN);
    float ip = 1.0f / fmaxf(sqrtf(sp), EPSN);

    // z[b, gi] = x[gi*128 + b]; z[b, 256+gi] = x_pair[gi*128 + b]
    int b  = row & 127;
    int gi = row >> 7;
    __nv_bfloat16* on = g_z + ((size_t)b * MSZ + gi) * DDIM;
    __nv_bfloat16* op = g_z + ((size_t)b * MSZ + 256 + gi) * DDIM;
    store_bf16x4(on, lane,      a0, ix);
    store_bf16x4(on, lane + 32, a1, ix);
    store_bf16x4(op, lane,      b0, ip);
    store_bf16x4(op, lane + 32, b1, ip);

    __shared__ float sm[8];
    if (lane == 0) sm[wid] = dp * ix * ip;
    __syncthreads();
    if (threadIdx.x == 0) {
        float t = 0.f;
        #pragma unroll
        for (int i = 0; i < 8; ++i) t += sm[i];
        g_pos_partials[blockIdx.x] = t;
    }
}

// ---------------------------------------------------------------------------
// Kernel 2: gram via mma.sync bf16, XOR-swizzled smem, 2 CTAs/SM
// CTA = (batch, 128-row i-tile): 512 CTAs, 256 threads
// 8 warps = 4 warp_m (32 rows) x 2 warp_n (16 cols of each 32-col B chunk)
// SMEM: A [128x256 bf16] 64KB + B double buffer 2 x [32x256 bf16] 16KB = 96KB
// j-loop: 16 chunks of 32 B-rows, cp.async double-buffered
// ---------------------------------------------------------------------------
#define A_BYTES   65536
#define CHB_BYTES 16384
#define SMEM_DYN  (A_BYTES + 2 * CHB_BYTES)   // 98,304 B -> 2 CTAs/SM

// physical byte offset of (row, 16B-seg) under XOR swizzle
__device__ __forceinline__ uint32_t swoff(int row, int seg) {
    return (uint32_t)row * 512u + (uint32_t)((seg ^ (row & 7)) << 4);
}

__device__ __forceinline__ void cp_rows(uint32_t dsm, const char* src,
                                        int nrows, int tid) {
    // nrows*32 16B segments, 256 threads
    int iters = nrows >> 3;                  // (nrows*32)/256
    for (int i = 0; i < iters; ++i) {
        int idx = tid + i * 256;
        int row = idx >> 5;
        int seg = idx & 31;
        asm volatile("cp.async.cg.shared.global [%0], [%1], 16;"
                     :: "r"(dsm + swoff(row, seg)),
                        "l"(src + (size_t)row * 512 + seg * 16) : "memory");
    }
}
#define CP_COMMIT() asm volatile("cp.async.commit_group;" ::: "memory")

__device__ __forceinline__ void ldsm_x4(uint32_t* r, uint32_t addr) {
    asm volatile("ldmatrix.sync.aligned.m8n8.x4.shared.b16 {%0,%1,%2,%3}, [%4];"
                 : "=r"(r[0]), "=r"(r[1]), "=r"(r[2]), "=r"(r[3]) : "r"(addr));
}
__device__ __forceinline__ void mma16816(float* c, const uint32_t* a,
                                         uint32_t b0, uint32_t b1) {
    asm volatile("mma.sync.aligned.m16n8k16.row.col.f32.bf16.bf16.f32 "
                 "{%0,%1,%2,%3}, {%4,%5,%6,%7}, {%8,%9}, {%0,%1,%2,%3};"
                 : "+f"(c[0]), "+f"(c[1]), "+f"(c[2]), "+f"(c[3])
                 : "r"(a[0]), "r"(a[1]), "r"(a[2]), "r"(a[3]), "r"(b0), "r"(b1));
}

__global__ __launch_bounds__(256, 2) void k_neg() {
    extern __shared__ char smraw[];
    const uint32_t sA  = smem_u32(smraw);
    const uint32_t sB0 = sA + A_BYTES;

    __shared__ float s_part[2][128];   // [warp_n][row]
    __shared__ float s_red[4];

    const int tid    = threadIdx.x;
    const int w      = tid >> 5;
    const int lane   = tid & 31;
    const int b      = blockIdx.x >> 2;
    const int it     = blockIdx.x & 3;          // 128-row i-tile
    const int warp_m = w & 3;                   // 4 M-slices of 32 rows
    const int warp_n = w >> 2;                  // 2 N-slices of 16 cols

    const char* zb = reinterpret_cast<const char*>(g_z) + (size_t)b * MSZ * DDIM * 2;

    // group 0: A(i-tile, 128 rows) + B chunk 0 (32 rows)
    cp_rows(sA,  zb + (size_t)it * 128 * 512, 128, tid);
    cp_rows(sB0, zb, 32, tid);
    CP_COMMIT();

    // per-thread ldmatrix addressing (swizzled)
    const int rowA  = warp_m * 32 + (lane & 15);
    const int mA    = rowA & 7;
    const int halfA = lane >> 4;
    const uint32_t aRow = sA + (uint32_t)rowA * 512u;

    const int rowB  = warp_n * 16 + ((lane >> 4) << 3) + (lane & 7);  // 0..31 in chunk
    const int mB    = rowB & 7;
    const int halfB = (lane >> 3) & 1;
    const uint32_t bRowOff = (uint32_t)rowB * 512u;

    float racc[4] = {0.f, 0.f, 0.f, 0.f};   // [mi][rowhalf]

    for (int c = 0; c < 16; ++c) {
        if (c < 15) {
            cp_rows(sB0 + (uint32_t)((c + 1) & 1) * CHB_BYTES,
                    zb + (size_t)(c + 1) * 32 * 512, 32, tid);
            CP_COMMIT();
            asm volatile("cp.async.wait_group 1;" ::: "memory");
        } else {
            asm volatile("cp.async.wait_group 0;" ::: "memory");
        }
        __syncthreads();                       // chunk c (and A) visible

        const uint32_t bBase = sB0 + (uint32_t)(c & 1) * CHB_BYTES + bRowOff;

        float acc[2][2][4];
        #pragma unroll
        for (int mi = 0; mi < 2; ++mi)
            #pragma unroll
            for (int ni = 0; ni < 2; ++ni)
                #pragma unroll
                for (int q = 0; q < 4; ++q) acc[mi][ni][q] = 0.f;

        #pragma unroll 8
        for (int ks = 0; ks < 16; ++ks) {
            uint32_t af0[4], af1[4], bf[4];
            uint32_t offA = (uint32_t)(((2 * ks + halfA) ^ mA) << 4);
            ldsm_x4(af0, aRow + offA);
            ldsm_x4(af1, aRow + 16u * 512u + offA);
            ldsm_x4(bf, bBase + (uint32_t)(((2 * ks + halfB) ^ mB) << 4));
            mma16816(acc[0][0], af0, bf[0], bf[1]);
            mma16816(acc[0][1], af0, bf[2], bf[3]);
            mma16816(acc[1][0], af1, bf[0], bf[1]);
            mma16816(acc[1][1], af1, bf[2], bf[3]);
        }

        // epilogue: exp(2*dot), mask diagonal, accumulate row partials
        const int gj0 = c * 32 + warp_n * 16 + (lane & 3) * 2;
        #pragma unroll
        for (int mi = 0; mi < 2; ++mi) {
            const int gi0 = it * 128 + warp_m * 32 + mi * 16 + (lane >> 2);
            #pragma unroll
            for (int ni = 0; ni < 2; ++ni) {
                const int gj = gj0 + ni * 8;
                float e00 = __expf(acc[mi][ni][0] * 2.f);
                float e01 = __expf(acc[mi][ni][1] * 2.f);
                float e10 = __expf(acc[mi][ni][2] * 2.f);
                float e11 = __expf(acc[mi][ni][3] * 2.f);
                if (gi0 == gj)         e00 = 0.f;
                if (gi0 == gj + 1)     e01 = 0.f;
                if (gi0 + 8 == gj)     e10 = 0.f;
                if (gi0 + 8 == gj + 1) e11 = 0.f;
                racc[mi * 2 + 0] += e00 + e01;
                racc[mi * 2 + 1] += e10 + e11;
            }
        }
        __syncthreads();                       // done reading chunk c buffer
    }

    // quad reduce (cols within warp), fixed-slot combine across warp_n
    #pragma unroll
    for (int s = 0; s < 4; ++s) {
        racc[s] += __shfl_xor_sync(0xFFFFFFFFu, racc[s], 1);
        racc[s] += __shfl_xor_sync(0xFFFFFFFFu, racc[s], 2);
    }
    if ((lane & 3) == 0) {
        #pragma unroll
        for (int s = 0; s < 4; ++s) {
            int row = warp_m * 32 + (s >> 1) * 16 + (s & 1) * 8 + (lane >> 2);
            s_part[warp_n][row] = racc[s];
        }
    }
    __syncthreads();

    // full row sums now in-CTA: log + block-reduce (deterministic)
    if (tid < 128) {
        float lg = logf(s_part[0][tid] + s_part[1][tid]);
        #pragma unroll
        for (int o = 16; o > 0; o >>= 1) lg += __shfl_xor_sync(0xFFFFFFFFu, lg, o);
        if (lane == 0) s_red[tid >> 5] = lg;
    }
    __syncthreads();
    if (tid == 0)
        g_neg_partials[blockIdx.x] = (s_red[0] + s_red[1]) + (s_red[2] + s_red[3]);
}

// ---------------------------------------------------------------------------
// Kernel 3: final deterministic reduction -> scalar loss
// ---------------------------------------------------------------------------
__global__ __launch_bounds__(256) void k_final(float* __restrict__ out) {
    __shared__ float rp[256], rn[256];
    int tid = threadIdx.x;
    float sp = 0.f, sn = 0.f;
    #pragma unroll
    for (int i = 0; i < 16; ++i) sp += g_pos_partials[tid + i * 256];
    sn = g_neg_partials[tid] + g_neg_partials[tid + 256];
    rp[tid] = sp; rn[tid] = sn;
    __syncthreads();
    for (int o = 128; o > 0; o >>= 1) {
        if (tid < o) { rp[tid] += rp[tid + o]; rn[tid] += rn[tid + o]; }
        __syncthreads();
    }
    if (tid == 0) {
        float loss_neg = rn[0] / (float)(NB * MSZ);
        float loss_pos = rp[0] * 2.0f / (float)NROWS;
        out[0] = loss_neg - loss_pos;
    }
}

// ---------------------------------------------------------------------------
extern "C" void kernel_launch(void* const* d_in, const int* in_sizes, int n_in,
                              void* d_out, int out_size) {
    const float* x  = (const float*)d_in[0];
    const float* xp = (const float*)d_in[1];
    float* out = (float*)d_out;

    cudaFuncSetAttribute(k_neg, cudaFuncAttributeMaxDynamicSharedMemorySize, SMEM_DYN);

    k_prep<<<NROWS / 8, 256>>>(x, xp);
    k_neg<<<NB * 4, 256, SMEM_DYN>>>();
    k_final<<<1, 256>>>(out);
}

// round 16
// speedup vs baseline: 1.6132x; 1.4717x over previous
#include <cuda_runtime.h>
#include <cuda_bf16.h>
#include <math.h>
#include <stdint.h>

// Problem constants
#define NROWS 32768      // rows in x (and in x_pair)
#define DDIM  256        // feature dim
#define NB    128        // 2B batches
#define MSZ   512        // mask size
#define EPSN  1e-8f

// Scratch
__device__ __align__(16) __nv_bfloat16 g_z[(size_t)NB * MSZ * DDIM];
__device__ float g_pos_partials[4096];
__device__ float g_row[NB][4][128];        // row-sums of exp per (b, i-block)
__device__ float g_col[NB][4][3][128];     // col-sum contribs: [b][dst block][src ti]
__device__ float g_neg_partials[NB];
__device__ int   g_cnt[NB];

__device__ __forceinline__ uint32_t smem_u32(const void* p) {
    uint32_t a;
    asm("{ .reg .u64 t; cvta.to.shared.u64 t, %1; cvt.u32.u64 %0, t; }" : "=r"(a) : "l"(p));
    return a;
}

// ---------------------------------------------------------------------------
// Kernel 1: per-row L2 normalize -> bf16 per-batch layout + pos partials
//           + zero per-batch counters
// ---------------------------------------------------------------------------
__device__ __forceinline__ void store_bf16x4(__nv_bfloat16* dst, int idx4,
                                             float4 v, float scale) {
    __nv_bfloat162 lo = __floats2bfloat162_rn(v.x * scale, v.y * scale);
    __nv_bfloat162 hi = __floats2bfloat162_rn(v.z * scale, v.w * scale);
    uint2 packed;
    packed.x = *reinterpret_cast<uint32_t*>(&lo);
    packed.y = *reinterpret_cast<uint32_t*>(&hi);
    reinterpret_cast<uint2*>(dst)[idx4] = packed;
}

__global__ __launch_bounds__(256) void k_prep(const float* __restrict__ x,
                                              const float* __restrict__ xp) {
    int wid  = threadIdx.x >> 5;
    int lane = threadIdx.x & 31;
    int row  = blockIdx.x * 8 + wid;

    if (blockIdx.x < NB && threadIdx.x == 0) g_cnt[blockIdx.x] = 0;

    const float4* xr = reinterpret_cast<const float4*>(x)  + (size_t)row * (DDIM / 4);
    const float4* pr = reinterpret_cast<const float4*>(xp) + (size_t)row * (DDIM / 4);

    float4 a0 = xr[lane];
    float4 a1 = xr[lane + 32];
    float4 b0 = pr[lane];
    float4 b1 = pr[lane + 32];

    float sx = a0.x*a0.x + a0.y*a0.y + a0.z*a0.z + a0.w*a0.w
             + a1.x*a1.x + a1.y*a1.y + a1.z*a1.z + a1.w*a1.w;
    float sp = b0.x*b0.x + b0.y*b0.y + b0.z*b0.z + b0.w*b0.w
             + b1.x*b1.x + b1.y*b1.y + b1.z*b1.z + b1.w*b1.w;
    float dp = a0.x*b0.x + a0.y*b0.y + a0.z*b0.z + a0.w*b0.w
             + a1.x*b1.x + a1.y*b1.y + a1.z*b1.z + a1.w*b1.w;

    #pragma unroll
    for (int o = 16; o > 0; o >>= 1) {
        sx += __shfl_xor_sync(0xFFFFFFFFu, sx, o);
        sp += __shfl_xor_sync(0xFFFFFFFFu, sp, o);
        dp += __shfl_xor_sync(0xFFFFFFFFu, dp, o);
    }

    float ix = 1.0f / fmaxf(sqrtf(sx), EPSN);
    float ip = 1.0f / fmaxf(sqrtf(sp), EPSN);

    // z[b, gi] = x[gi*128 + b]; z[b, 256+gi] = x_pair[gi*128 + b]
    int b  = row & 127;
    int gi = row >> 7;
    __nv_bfloat16* on = g_z + ((size_t)b * MSZ + gi) * DDIM;
    __nv_bfloat16* op = g_z + ((size_t)b * MSZ + 256 + gi) * DDIM;
    store_bf16x4(on, lane,      a0, ix);
    store_bf16x4(on, lane + 32, a1, ix);
    store_bf16x4(op, lane,      b0, ip);
    store_bf16x4(op, lane + 32, b1, ip);

    __shared__ float sm[8];
    if (lane == 0) sm[wid] = dp * ix * ip;
    __syncthreads();
    if (threadIdx.x == 0) {
        float t = 0.f;
        #pragma unroll
        for (int i = 0; i < 8; ++i) t += sm[i];
        g_pos_partials[blockIdx.x] = t;
    }
}

// ---------------------------------------------------------------------------
// Kernel 2: symmetric gram via mma.sync bf16 — upper-triangle tiles only
// CTA = (ti, b): grid 512, heavy panels (ti=0) first. 256 threads.
// Tiles (ti, tj) for tj >= ti: diagonal tile uses A as both operands.
// SMEM: A panel [128x256 bf16] + B double buffer, padded stride 528B.
// ---------------------------------------------------------------------------
#define AB_STRIDE 528                 // 512B row + 16B pad (conflict-free ldmatrix)
#define TILE_B    (128 * AB_STRIDE)   // 67,584 B
#define SMEM_DYN  (3 * TILE_B)        // 202,752 B

__device__ __forceinline__ void cp_tile(char* dst, const char* src, int tid) {
    uint32_t d = smem_u32(dst);
    #pragma unroll
    for (int i = 0; i < 16; ++i) {
        int idx = tid + i * 256;       // 0..4095: 128 rows x 32 segs of 16B
        int row = idx >> 5;
        int seg = idx & 31;
        asm volatile("cp.async.cg.shared.global [%0], [%1], 16;"
                     :: "r"(d + row * AB_STRIDE + seg * 16),
                        "l"(src + (size_t)row * 512 + seg * 16) : "memory");
    }
}
#define CP_COMMIT() asm volatile("cp.async.commit_group;" ::: "memory")

__device__ __forceinline__ void ldsm_x4(uint32_t* r, uint32_t addr) {
    asm volatile("ldmatrix.sync.aligned.m8n8.x4.shared.b16 {%0,%1,%2,%3}, [%4];"
                 : "=r"(r[0]), "=r"(r[1]), "=r"(r[2]), "=r"(r[3]) : "r"(addr));
}
__device__ __forceinline__ void mma16816(float* c, const uint32_t* a,
                                         uint32_t b0, uint32_t b1) {
    asm volatile("mma.sync.aligned.m16n8k16.row.col.f32.bf16.bf16.f32 "
                 "{%0,%1,%2,%3}, {%4,%5,%6,%7}, {%8,%9}, {%0,%1,%2,%3};"
                 : "+f"(c[0]), "+f"(c[1]), "+f"(c[2]), "+f"(c[3])
                 : "r"(a[0]), "r"(a[1]), "r"(a[2]), "r"(a[3]), "r"(b0), "r"(b1));
}

__global__ __launch_bounds__(256, 1) void k_neg() {
    extern __shared__ char smraw[];
    char* sA = smraw;
    char* sBb[2] = { smraw + TILE_B, smraw + 2 * TILE_B };
    __shared__ float s_part[2][128];   // [warp_n][row] row partials
    __shared__ float s_col[4][128];    // [warp_m][col] col partials (per tile)
    __shared__ int   s_last;

    const int tid    = threadIdx.x;
    const int w      = tid >> 5;
    const int lane   = tid & 31;
    const int ti     = blockIdx.x >> 7;         // heavy (ti=0) CTAs first
    const int b      = blockIdx.x & 127;
    const int warp_m = w & 3;                   // 4 M-slices of 32 rows
    const int warp_n = w >> 2;                  // 2 N-slices of 64 cols

    const char* zb = reinterpret_cast<const char*>(g_z) + (size_t)b * MSZ * DDIM * 2;

    // prefetch: A panel (group), then B(ti+1) (group)
    cp_tile(sA, zb + (size_t)ti * 128 * 512, tid);
    CP_COMMIT();
    if (ti < 3) {
        cp_tile(sBb[(ti + 1) & 1], zb + (size_t)(ti + 1) * 128 * 512, tid);
        CP_COMMIT();
        asm volatile("cp.async.wait_group 1;" ::: "memory");   // A ready
    } else {
        asm volatile("cp.async.wait_group 0;" ::: "memory");
    }
    __syncthreads();

    const uint32_t aBase = smem_u32(sA)
        + (uint32_t)(warp_m * 32 + (lane & 15)) * AB_STRIDE + (uint32_t)(lane >> 4) * 16;
    const uint32_t bOff  =
          (uint32_t)(warp_n * 64 + (lane >> 4) * 8 + (lane & 7)) * AB_STRIDE
        + (uint32_t)((lane >> 3) & 1) * 16;

    float racc[4] = {0.f, 0.f, 0.f, 0.f};   // row partials [mi][rowhalf]

    for (int tj = ti; tj <= 3; ++tj) {
        const bool diag = (tj == ti);
        if (!diag) {   // arrange B(tj) ready; prefetch B(tj+1)
            if (tj < 3) {
                cp_tile(sBb[(tj + 1) & 1], zb + (size_t)(tj + 1) * 128 * 512, tid);
                CP_COMMIT();
                asm volatile("cp.async.wait_group 1;" ::: "memory");
            } else {
                asm volatile("cp.async.wait_group 0;" ::: "memory");
            }
            __syncthreads();               // B(tj) visible
        }
        const uint32_t bBase = (diag ? smem_u32(sA) : smem_u32(sBb[tj & 1])) + bOff;

        float acc[2][8][4];
        #pragma unroll
        for (int mi = 0; mi < 2; ++mi)
            #pragma unroll
            for (int ni = 0; ni < 8; ++ni)
                #pragma unroll
                for (int q = 0; q < 4; ++q) acc[mi][ni][q] = 0.f;

        #pragma unroll 4
        for (int ks = 0; ks < 16; ++ks) {
            uint32_t af[2][4];
            ldsm_x4(af[0], aBase + ks * 32);
            ldsm_x4(af[1], aBase + 16 * AB_STRIDE + ks * 32);
            #pragma unroll
            for (int p = 0; p < 4; ++p) {
                uint32_t bf[4];
                ldsm_x4(bf, bBase + p * 16 * AB_STRIDE + ks * 32);
                #pragma unroll
                for (int mi = 0; mi < 2; ++mi) {
                    mma16816(acc[mi][p * 2 + 0], af[mi], bf[0], bf[1]);
                    mma16816(acc[mi][p * 2 + 1], af[mi], bf[2], bf[3]);
                }
            }
        }

        // epilogue: exp(2*dot); rows always; cols too when off-diagonal
        float colp[8][2];
        #pragma unroll
        for (int ni = 0; ni < 8; ++ni) { colp[ni][0] = 0.f; colp[ni][1] = 0.f; }

        const int lj0 = warp_n * 64 + (lane & 3) * 2;   // col within tile
        #pragma unroll
        for (int mi = 0; mi < 2; ++mi) {
            const int li0 = warp_m * 32 + mi * 16 + (lane >> 2);  // row within tile
            #pragma unroll
            for (int ni = 0; ni < 8; ++ni) {
                const int lj = lj0 + ni * 8;
                float e00 = __expf(acc[mi][ni][0] * 2.f);
                float e01 = __expf(acc[mi][ni][1] * 2.f);
                float e10 = __expf(acc[mi][ni][2] * 2.f);
                float e11 = __expf(acc[mi][ni][3] * 2.f);
                if (diag) {
                    if (li0 == lj)         e00 = 0.f;
                    if (li0 == lj + 1)     e01 = 0.f;
                    if (li0 + 8 == lj)     e10 = 0.f;
                    if (li0 + 8 == lj + 1) e11 = 0.f;
                }
                racc[mi * 2 + 0] += e00 + e01;
                racc[mi * 2 + 1] += e10 + e11;
                colp[ni][0] += e00 + e10;
                colp[ni][1] += e01 + e11;
            }
        }

        if (!diag) {
            // reduce cols over the 8 row-groups (lane>>2) within the warp
            #pragma unroll
            for (int ni = 0; ni < 8; ++ni)
                #pragma unroll
                for (int q = 0; q < 2; ++q) {
                    colp[ni][q] += __shfl_xor_sync(0xFFFFFFFFu, colp[ni][q], 4);
                    colp[ni][q] += __shfl_xor_sync(0xFFFFFFFFu, colp[ni][q], 8);
                    colp[ni][q] += __shfl_xor_sync(0xFFFFFFFFu, colp[ni][q], 16);
                }
            if (lane < 4) {
                #pragma unroll
                for (int ni = 0; ni < 8; ++ni) {
                    int col = warp_n * 64 + ni * 8 + lane * 2;
                    s_col[warp_m][col]     = colp[ni][0];
                    s_col[warp_m][col + 1] = colp[ni][1];
                }
            }
            __syncthreads();
            if (tid < 128) {
                float cs = ((s_col[0][tid] + s_col[1][tid])
                          + (s_col[2][tid] + s_col[3][tid]));
                g_col[b][tj][ti][tid] = cs;    // written exactly once
            }
            __syncthreads();   // s_col reusable + B buffer reads done
        }
    }

    // row partials: quad reduce, fixed-slot combine across warp_n, store once
    #pragma unroll
    for (int s = 0; s < 4; ++s) {
        racc[s] += __shfl_xor_sync(0xFFFFFFFFu, racc[s], 1);
        racc[s] += __shfl_xor_sync(0xFFFFFFFFu, racc[s], 2);
    }
    if ((lane & 3) == 0) {
        #pragma unroll
        for (int s = 0; s < 4; ++s) {
            int row = warp_m * 32 + (s >> 1) * 16 + (s & 1) * 8 + (lane >> 2);
            s_part[warp_n][row] = racc[s];
        }
    }
    __syncthreads();
    if (tid < 128) g_row[b][ti][tid] = s_part[0][tid] + s_part[1][tid];

    // completion protocol: 4th CTA of this batch finalizes (deterministic math)
    __threadfence();
    __syncthreads();
    if (tid == 0) s_last = atomicAdd(&g_cnt[b], 1);
    __syncthreads();
    if (s_last == 3) {
        __threadfence();
        float lg = 0.f;
        #pragma unroll
        for (int rr2 = 0; rr2 < 2; ++rr2) {
            int r  = tid + rr2 * 256;        // 0..511
            int t  = r >> 7;
            int rr = r & 127;
            float v = g_row[b][t][rr];
            for (int src = 0; src < t; ++src) v += g_col[b][t][src][rr];
            lg += logf(v);
        }
        #pragma unroll
        for (int o = 16; o > 0; o >>= 1) lg += __shfl_xor_sync(0xFFFFFFFFu, lg, o);
        __shared__ float s_red[8];
        if (lane == 0) s_red[w] = lg;
        __syncthreads();
        if (tid == 0) {
            float t = 0.f;
            #pragma unroll
            for (int i = 0; i < 8; ++i) t += s_red[i];
            g_neg_partials[b] = t;
        }
    }
}

// ---------------------------------------------------------------------------
// Kernel 3: final deterministic reduction -> scalar loss
// ---------------------------------------------------------------------------
__global__ __launch_bounds__(256) void k_final(float* __restrict__ out) {
    __shared__ float rp[256], rn[256];
    int tid = threadIdx.x;
    float sp = 0.f;
    #pragma unroll
    for (int i = 0; i < 16; ++i) sp += g_pos_partials[tid + i * 256];
    rp[tid] = sp;
    rn[tid] = (tid < NB) ? g_neg_partials[tid] : 0.f;
    __syncthreads();
    for (int o = 128; o > 0; o >>= 1) {
        if (tid < o) { rp[tid] += rp[tid + o]; rn[tid] += rn[tid + o]; }
        __syncthreads();
    }
    if (tid == 0) {
        float loss_neg = rn[0] / (float)(NB * MSZ);
        float loss_pos = rp[0] * 2.0f / (float)NROWS;
        out[0] = loss_neg - loss_pos;
    }
}

// ---------------------------------------------------------------------------
extern "C" void kernel_launch(void* const* d_in, const int* in_sizes, int n_in,
                              void* d_out, int out_size) {
    const float* x  = (const float*)d_in[0];
    const float* xp = (const float*)d_in[1];
    float* out = (float*)d_out;

    cudaFuncSetAttribute(k_neg, cudaFuncAttributeMaxDynamicSharedMemorySize, SMEM_DYN);

    k_prep<<<NROWS / 8, 256>>>(x, xp);
    k_neg<<<NB * 4, 256, SMEM_DYN>>>();
    k_final<<<1, 256>>>(out);
}